// round 1
// baseline (speedup 1.0000x reference)
#include <cuda_runtime.h>

#define TT 500
#define BB 64
#define FF 256
#define HH 512
#define OO 128
#define NBLK 128   // scan blocks: 16 h-chunks x 8 batch-chunks

// ---- scratch (device globals: no allocation allowed) ----
__device__ float    g_xproj[(size_t)TT * BB * HH];     // 65.5 MB
__device__ unsigned g_spk[(size_t)TT * BB * (HH / 32)]; // 2 MB spike bitmasks
__device__ float    g_lin[(size_t)TT * BB * OO];       // 16 MB
__device__ float    g_woutT[HH * OO];                  // 256 KB
__device__ unsigned g_flags[NBLK];                     // barrier flags (zero-init, reset by k_filter)

// ============================================================
// K0: transpose w_out [O,H] -> g_woutT [H,O]
// ============================================================
__global__ void k_wtrans(const float* __restrict__ w_out) {
    int idx = blockIdx.x * blockDim.x + threadIdx.x;   // = h*128 + o
    if (idx < HH * OO) {
        int h = idx >> 7, o = idx & 127;
        g_woutT[idx] = w_out[o * HH + h];
    }
}

// ============================================================
// K1: x_proj[m,h] = sum_f x[m,f] * w_in[h,f]   (M=32000,K=256,N=512)
// classic 64x64 tile, 256 threads, 4x4 per thread, fp32
// ============================================================
__global__ void __launch_bounds__(256) k_xproj(const float* __restrict__ A,
                                               const float* __restrict__ B) {
    __shared__ float As[32 * 65];
    __shared__ float Bs[32 * 65];
    int tid = threadIdx.x;
    int tx = tid & 15, ty = tid >> 4;
    int mBase = blockIdx.x * 64;
    int nBase = blockIdx.y * 64;
    float acc[4][4] = {};
    for (int k0 = 0; k0 < FF; k0 += 32) {
#pragma unroll
        for (int r = 0; r < 2; r++) {
            int li = tid + r * 256;       // 0..511
            int row = li >> 3;            // 0..63
            int kq = li & 7;              // float4 within 32-wide k tile
            float4 va = *(const float4*)(A + (size_t)(mBase + row) * FF + k0 + kq * 4);
            As[(kq * 4 + 0) * 65 + row] = va.x;
            As[(kq * 4 + 1) * 65 + row] = va.y;
            As[(kq * 4 + 2) * 65 + row] = va.z;
            As[(kq * 4 + 3) * 65 + row] = va.w;
            float4 vb = *(const float4*)(B + (size_t)(nBase + row) * FF + k0 + kq * 4);
            Bs[(kq * 4 + 0) * 65 + row] = vb.x;
            Bs[(kq * 4 + 1) * 65 + row] = vb.y;
            Bs[(kq * 4 + 2) * 65 + row] = vb.z;
            Bs[(kq * 4 + 3) * 65 + row] = vb.w;
        }
        __syncthreads();
#pragma unroll
        for (int k = 0; k < 32; k++) {
            float a[4], b[4];
#pragma unroll
            for (int i2 = 0; i2 < 4; i2++) {
                a[i2] = As[k * 65 + ty * 4 + i2];
                b[i2] = Bs[k * 65 + tx * 4 + i2];
            }
#pragma unroll
            for (int i2 = 0; i2 < 4; i2++)
#pragma unroll
                for (int j = 0; j < 4; j++)
                    acc[i2][j] += a[i2] * b[j];
        }
        __syncthreads();
    }
#pragma unroll
    for (int i2 = 0; i2 < 4; i2++) {
        float4 v = make_float4(acc[i2][0], acc[i2][1], acc[i2][2], acc[i2][3]);
        *(float4*)(g_xproj + (size_t)(mBase + ty * 4 + i2) * HH + nBase + tx * 4) = v;
    }
}

// ============================================================
// K2: persistent LIF-AdEx scan. 128 blocks x 256 threads.
//  block = (hb = bid&15 : 32 h rows, bb = bid>>4 : 8 batches)
//  warp w -> batch bb*8+w ; lane -> h = hb*32+lane
//  W_rec slice transposed in smem: wT[c*32 + r] = w_rec[hb*32+r][c]
//  spikes exchanged as 32-bit ballot words in g_spk[t][b][16]
//  barrier: per-block flag, 128 pollers
// ============================================================
__global__ void __launch_bounds__(256, 1) k_scan(const float* __restrict__ w_rec,
                                                 float* __restrict__ d_out) {
    extern __shared__ float smem[];
    float* wT = smem;                               // 512*32 floats
    unsigned* zs = (unsigned*)(smem + HH * 32);     // 128 words: [b_local][16]

    int tid = threadIdx.x;
    int bid = blockIdx.x;
    int hb = bid & 15, bb = bid >> 4;
    int lane = tid & 31, warp = tid >> 5;
    int b = bb * 8 + warp;
    int h = hb * 32 + lane;

    // load W_rec slice (transposed). one-time.
    for (int idx = tid; idx < HH * 32; idx += 256) {
        int r = idx & 31, c = idx >> 5;
        wT[idx] = w_rec[(size_t)(hb * 32 + r) * HH + c];
    }
    __syncthreads();

    volatile unsigned* vflags = (volatile unsigned*)g_flags;

    float v = 0.f, cur = 0.f, a = 0.f;
    bool z = false;
    float xp_next = g_xproj[(size_t)b * HH + h];  // t=0 prefetch

    for (int t = 0; t < TT; t++) {
        float irec = 0.f;
        if (t > 0) {
            if (tid < 128) {
                while (vflags[tid] < (unsigned)t) { }
                __threadfence();
            }
            __syncthreads();
            if (tid < 128) {
                int bl = tid >> 4, w16 = tid & 15;
                zs[tid] = g_spk[(size_t)((t - 1) * BB + bb * 8 + bl) * 16 + w16];
            }
            __syncthreads();
            const unsigned* zrow = zs + warp * 16;
#pragma unroll
            for (int w16 = 0; w16 < 16; w16++) {
                unsigned m = zrow[w16];
                const float* wp = wT + w16 * 32 * 32 + lane;
                while (m) {
                    int j = __ffs(m) - 1;
                    m &= m - 1;
                    irec += wp[j * 32];
                }
            }
        }

        float xp = xp_next;
        if (t + 1 < TT) xp_next = g_xproj[(size_t)((t + 1) * BB + b) * HH + h];

        // LIF-AdEx step (all from OLD state; ordering matches reference)
        float ex = expf((v - 1.0f) * 2.0f);                       // exp((v-V_TH)/DELTA_T)
        float dv = 0.1f * ((((0.0f - v) + 0.5f * ex) + cur) - a); // DT*TAU_MEM_INV*(...)
        float v_dec = v + dv;
        float i_dec = cur - 0.2f * cur;                           // DT*TAU_SYN_INV
        float a_dec = a + 0.002f * (4.0f * v - a);                // DT*TAU_ADA_INV, ADAPT_CURRENT
        z = (v_dec - 1.0f) > 0.0f;
        v = z ? 0.0f : v_dec;
        cur = (i_dec + xp) + irec;
        a = a_dec + (z ? 0.02f : 0.0f);

        unsigned bits = __ballot_sync(0xffffffffu, z);
        if (lane == 0) g_spk[(size_t)(t * BB + b) * 16 + hb] = bits;

        __syncthreads();
        if (tid == 0) {
            __threadfence();
            ((volatile unsigned*)g_flags)[bid] = (unsigned)(t + 1);
        }
    }

    // final states (z, v, i, a) appended after out[T,B,O]
    size_t base = (size_t)TT * BB * OO;
    size_t off = (size_t)b * HH + h;
    d_out[base + off] = z ? 1.0f : 0.0f;
    d_out[base + BB * HH + off] = v;
    d_out[base + 2 * BB * HH + off] = cur;
    d_out[base + 3 * BB * HH + off] = a;
}

// ============================================================
// K3: lin[t,b,o] = b_out[o] + sum over spiking h of w_outT[h][o]
// one block per (t,b), 128 threads (one per o)
// ============================================================
__global__ void __launch_bounds__(128) k_lin(const float* __restrict__ b_out) {
    __shared__ unsigned zw[16];
    int tb = blockIdx.x;
    int tid = threadIdx.x;
    if (tid < 16) zw[tid] = g_spk[(size_t)tb * 16 + tid];
    __syncthreads();
    float acc = 0.f;
#pragma unroll
    for (int w16 = 0; w16 < 16; w16++) {
        unsigned m = zw[w16];
        const float* wp = g_woutT + (size_t)w16 * 32 * OO + tid;
        while (m) {
            int j = __ffs(m) - 1;
            m &= m - 1;
            acc += wp[j * OO];
        }
    }
    g_lin[(size_t)tb * OO + tid] = acc + b_out[tid];
}

// ============================================================
// K4: exponential filter over t per (b,o); also resets barrier flags
// ============================================================
__global__ void __launch_bounds__(128) k_filter(float* __restrict__ out) {
    int b = blockIdx.x;       // 64
    int o = threadIdx.x;      // 128
    if (b == 0) ((volatile unsigned*)g_flags)[o] = 0;  // deterministic replays
    const float C = (float)(0.001 * 223.1435511314);
    float y = 0.f;
    for (int t = 0; t < TT; t++) {
        float l = g_lin[((size_t)t * BB + b) * OO + o];
        y = y + C * (l - y);
        out[((size_t)t * BB + b) * OO + o] = y;
    }
}

// ============================================================
extern "C" void kernel_launch(void* const* d_in, const int* in_sizes, int n_in,
                              void* d_out, int out_size) {
    const float* x     = (const float*)d_in[0];  // [500,64,256]
    const float* w_in  = (const float*)d_in[1];  // [512,256]
    const float* w_rec = (const float*)d_in[2];  // [512,512]
    const float* w_out = (const float*)d_in[3];  // [128,512]
    const float* b_out = (const float*)d_in[4];  // [128]
    float* out = (float*)d_out;

    const int scan_smem = HH * 32 * 4 + 128 * 4;  // 66048 B
    cudaFuncSetAttribute(k_scan, cudaFuncAttributeMaxDynamicSharedMemorySize, scan_smem);

    k_wtrans<<<(HH * OO + 255) / 256, 256>>>(w_out);
    k_xproj<<<dim3((TT * BB) / 64, HH / 64), 256>>>(x, w_in);
    k_scan<<<NBLK, 256, scan_smem>>>(w_rec, out);
    k_lin<<<TT * BB, 128>>>(b_out);
    k_filter<<<BB, 128>>>(out);
}

// round 3
// speedup vs baseline: 2.4561x; 2.4561x over previous
#include <cuda_runtime.h>
#include <cstdint>

#define TT 500
#define BB 64
#define FF 256
#define HH 512
#define OO 128

#define CL 8      // CTAs per cluster (one batch group)
#define HC 64     // h rows per CTA
#define WS 65     // padded smem stride for wT

// ---- scratch (device globals: no allocation allowed) ----
__device__ float    g_xproj[(size_t)TT * BB * HH];      // 65.5 MB
__device__ unsigned g_spk[(size_t)TT * BB * (HH / 32)]; // 2 MB spike bitmasks
__device__ float    g_lin[(size_t)TT * BB * OO];        // 16 MB
__device__ float    g_woutT[HH * OO];                   // 256 KB

// ============================================================
// K0: transpose w_out [O,H] -> g_woutT [H,O]
// ============================================================
__global__ void k_wtrans(const float* __restrict__ w_out) {
    int idx = blockIdx.x * blockDim.x + threadIdx.x;
    if (idx < HH * OO) {
        int h = idx >> 7, o = idx & 127;
        g_woutT[idx] = w_out[o * HH + h];
    }
}

// ============================================================
// K1: x_proj[m,h] = sum_f x[m,f] * w_in[h,f]  (M=32000,K=256,N=512)
// 128x128 tile, BK=16, 256 threads, 8x8 per thread
// ============================================================
__global__ void __launch_bounds__(256) k_xproj(const float* __restrict__ A,
                                               const float* __restrict__ B) {
    __shared__ float As[16][132];
    __shared__ float Bs[16][132];
    int tid = threadIdx.x;
    int tx = tid & 15, ty = tid >> 4;     // 16 x 16 thread grid
    int mBase = blockIdx.x * 128;
    int nBase = blockIdx.y * 128;
    float acc[8][8] = {};
    for (int k0 = 0; k0 < FF; k0 += 16) {
#pragma unroll
        for (int i = 0; i < 2; i++) {
            int li = tid + i * 256;       // 0..511
            int row = li >> 2;            // 0..127
            int c4 = li & 3;              // float4 index within 16-wide k panel
            float4 va = *(const float4*)(A + (size_t)(mBase + row) * FF + k0 + c4 * 4);
            As[c4 * 4 + 0][row] = va.x;
            As[c4 * 4 + 1][row] = va.y;
            As[c4 * 4 + 2][row] = va.z;
            As[c4 * 4 + 3][row] = va.w;
            float4 vb = *(const float4*)(B + (size_t)(nBase + row) * FF + k0 + c4 * 4);
            Bs[c4 * 4 + 0][row] = vb.x;
            Bs[c4 * 4 + 1][row] = vb.y;
            Bs[c4 * 4 + 2][row] = vb.z;
            Bs[c4 * 4 + 3][row] = vb.w;
        }
        __syncthreads();
#pragma unroll
        for (int k = 0; k < 16; k++) {
            float a[8], b[8];
            *(float4*)(a)     = *(const float4*)&As[k][ty * 8];
            *(float4*)(a + 4) = *(const float4*)&As[k][ty * 8 + 4];
            *(float4*)(b)     = *(const float4*)&Bs[k][tx * 8];
            *(float4*)(b + 4) = *(const float4*)&Bs[k][tx * 8 + 4];
#pragma unroll
            for (int i2 = 0; i2 < 8; i2++)
#pragma unroll
                for (int j = 0; j < 8; j++)
                    acc[i2][j] += a[i2] * b[j];
        }
        __syncthreads();
    }
#pragma unroll
    for (int i2 = 0; i2 < 8; i2++) {
        float* op = g_xproj + (size_t)(mBase + ty * 8 + i2) * HH + nBase + tx * 8;
        *(float4*)(op)     = make_float4(acc[i2][0], acc[i2][1], acc[i2][2], acc[i2][3]);
        *(float4*)(op + 4) = make_float4(acc[i2][4], acc[i2][5], acc[i2][6], acc[i2][7]);
    }
}

// ============================================================
// K2: persistent LIF-AdEx scan with CGA clusters.
//  8 clusters (one per batch group of 8 batches) x 8 CTAs (64 h each).
//  Spikes exchanged as ballot words via DSMEM double-buffered mailboxes;
//  ONE barrier.cluster per step (arrive=release / wait=acquire).
//  512 threads: warp w -> batch_local w>>1, h-half w&1.
// ============================================================
__global__ void __launch_bounds__(512, 1) __cluster_dims__(CL, 1, 1)
k_scan(const float* __restrict__ w_rec, float* __restrict__ d_out) {
    extern __shared__ float smem[];
    float* wT = smem;                                  // [512][WS] transposed slice
    unsigned* mbox = (unsigned*)(smem + HH * WS);      // [2][8][2] ballot words

    int tid = threadIdx.x;
    int lane = tid & 31, warp = tid >> 5;              // warp 0..15
    int bl = warp >> 1;                                // batch_local 0..7
    int half = warp & 1;
    unsigned r;
    asm("mov.u32 %0, %%cluster_ctarank;" : "=r"(r));   // 0..7
    int g = blockIdx.x >> 3;                           // batch group 0..7
    int b = g * 8 + bl;
    int hl = half * 32 + lane;                         // 0..63
    int h = (int)r * HC + hl;

    // load transposed W_rec slice: wT[j*WS + hh] = w_rec[r*64+hh][j]
    for (int idx = tid; idx < HH * HC; idx += 512) {
        int j = idx & (HH - 1);       // column (source h index)
        int hh = idx >> 9;            // 0..63 (our local row)
        wT[(size_t)j * WS + hh] = w_rec[(size_t)((int)r * HC + hh) * HH + j];
    }
    __syncthreads();

    uint32_t mbox_u32;
    {
        uint64_t tmp;
        asm("cvta.to.shared.u64 %0, %1;" : "=l"(tmp) : "l"(mbox));
        mbox_u32 = (uint32_t)tmp;
    }

    float v = 0.f, cur = 0.f, aa = 0.f;
    bool z = false;
    float xp_next = g_xproj[(size_t)b * HH + h];  // t=0 prefetch

    for (int t = 0; t < TT; t++) {
        float irec = 0.f;
        if (t > 0) {
            int buf = (t - 1) & 1;
            unsigned val = 0;
            if (lane < 16) {
                int srcr = lane >> 1;
                uint32_t la = mbox_u32 + (unsigned)(((buf * 8 + bl) * 2 + (lane & 1)) * 4);
                uint32_t pa;
                asm("mapa.shared::cluster.u32 %0, %1, %2;" : "=r"(pa) : "r"(la), "r"(srcr));
                asm("ld.shared::cluster.b32 %0, [%1];" : "=r"(val) : "r"(pa));
            }
#pragma unroll
            for (int w16 = 0; w16 < 16; w16++) {
                unsigned m = __shfl_sync(0xffffffffu, val, w16);
                const float* wp = wT + (size_t)(w16 * 32) * WS + hl;
                while (m) {
                    int j = __ffs(m) - 1;
                    m &= m - 1;
                    irec += wp[(size_t)j * WS];
                }
            }
        }

        float xp = xp_next;
        if (t + 1 < TT) xp_next = g_xproj[(size_t)((t + 1) * BB + b) * HH + h];

        // LIF-AdEx step (all from OLD state; ordering matches reference)
        float ex = expf((v - 1.0f) * 2.0f);                       // exp((v-V_TH)/DELTA_T)
        float dv = 0.1f * ((((0.0f - v) + 0.5f * ex) + cur) - aa);
        float v_dec = v + dv;
        float i_dec = cur - 0.2f * cur;
        float a_dec = aa + 0.002f * (4.0f * v - aa);
        z = (v_dec - 1.0f) > 0.0f;
        v = z ? 0.0f : v_dec;
        cur = (i_dec + xp) + irec;
        aa = a_dec + (z ? 0.02f : 0.0f);

        unsigned bits = __ballot_sync(0xffffffffu, z);
        if (lane == 0) {
            mbox[((t & 1) * 8 + bl) * 2 + half] = bits;                      // cluster mailbox
            g_spk[(size_t)(t * BB + b) * 16 + (int)r * 2 + half] = bits;     // record for k_lin
        }

        // one cluster barrier per step: release STS, acquire peer smem
        asm volatile("barrier.cluster.arrive.aligned;" ::: "memory");
        asm volatile("barrier.cluster.wait.aligned;" ::: "memory");
    }

    // final states (z, v, i, a) appended after out[T,B,O]
    size_t base = (size_t)TT * BB * OO;
    size_t off = (size_t)b * HH + h;
    d_out[base + off] = z ? 1.0f : 0.0f;
    d_out[base + BB * HH + off] = v;
    d_out[base + 2 * BB * HH + off] = cur;
    d_out[base + 3 * BB * HH + off] = aa;
}

// ============================================================
// K3: lin[t,b,o] = b_out[o] + sum over spiking h of w_outT[h][o]
// ============================================================
__global__ void __launch_bounds__(128) k_lin(const float* __restrict__ b_out) {
    __shared__ unsigned zw[16];
    int tb = blockIdx.x;
    int tid = threadIdx.x;
    if (tid < 16) zw[tid] = g_spk[(size_t)tb * 16 + tid];
    __syncthreads();
    float acc = 0.f;
#pragma unroll
    for (int w16 = 0; w16 < 16; w16++) {
        unsigned m = zw[w16];
        const float* wp = g_woutT + (size_t)w16 * 32 * OO + tid;
        while (m) {
            int j = __ffs(m) - 1;
            m &= m - 1;
            acc += wp[j * OO];
        }
    }
    g_lin[(size_t)tb * OO + tid] = acc + b_out[tid];
}

// ============================================================
// K4: exponential filter over t per (b,o)
// ============================================================
__global__ void __launch_bounds__(128) k_filter(float* __restrict__ out) {
    int b = blockIdx.x;       // 64
    int o = threadIdx.x;      // 128
    const float C = (float)(0.001 * 223.1435511314);
    float y = 0.f;
    for (int t = 0; t < TT; t++) {
        float l = g_lin[((size_t)t * BB + b) * OO + o];
        y = y + C * (l - y);
        out[((size_t)t * BB + b) * OO + o] = y;
    }
}

// ============================================================
extern "C" void kernel_launch(void* const* d_in, const int* in_sizes, int n_in,
                              void* d_out, int out_size) {
    const float* x     = (const float*)d_in[0];  // [500,64,256]
    const float* w_in  = (const float*)d_in[1];  // [512,256]
    const float* w_rec = (const float*)d_in[2];  // [512,512]
    const float* w_out = (const float*)d_in[3];  // [128,512]
    const float* b_out = (const float*)d_in[4];  // [128]
    float* out = (float*)d_out;

    const int scan_smem = HH * WS * 4 + 2 * 8 * 2 * 4;  // 133248 B
    static bool attr_set = false;
    if (!attr_set) {
        cudaFuncSetAttribute(k_scan, cudaFuncAttributeMaxDynamicSharedMemorySize, scan_smem);
        attr_set = true;
    }

    k_wtrans<<<(HH * OO + 255) / 256, 256>>>(w_out);
    k_xproj<<<dim3((TT * BB) / 128, HH / 128), 256>>>(x, w_in);
    k_scan<<<CL * 8, 512, scan_smem>>>(w_rec, out);
    k_lin<<<TT * BB, 128>>>(b_out);
    k_filter<<<BB, 128>>>(out);
}